// round 6
// baseline (speedup 1.0000x reference)
#include <cuda_runtime.h>

#define SS   16
#define IND  128
#define OUTD 64
#define ED   32
#define OSTR 160     // output row: [x(64) | h_prime(64) | h_edge(32)]
#define MT   32      // nodes per block
#define NTH  256
#define RPAD 132     // padded smem row (floats), 16B-aligned, conflict-free
#define PF   4

// ---- device-global constants (allocation-free) ----
__device__ float g_w2a[IND];    // W2 @ a_n
__device__ float g_wax[IND];    // W  @ a_x

// ---------------------------------------------------------------------------
__global__ void prelude(const float* __restrict__ W, const float* __restrict__ W2,
                        const float* __restrict__ a) {
    int k = threadIdx.x;                        // 0..127
    float s1 = 0.f, s2 = 0.f;
#pragma unroll
    for (int d = 0; d < OUTD; ++d) {
        s1 = fmaf(W [k * OUTD + d], a[d],        s1);
        s2 = fmaf(W2[k * OUTD + d], a[OUTD + d], s2);
    }
    g_wax[k] = s1;
    g_w2a[k] = s2;
}

// ---------------------------------------------------------------------------
// Fully fused: stage input -> warp-per-node online-softmax attention
// (agg kept in smem) -> in-block dual GEMM (x = in@W | h' = agg@W2).
// ---------------------------------------------------------------------------
__global__ __launch_bounds__(NTH, 3)
void fused(const float* __restrict__ input, const float* __restrict__ neigh,
           const float* __restrict__ ee, const float* __restrict__ a,
           const float* __restrict__ W, const float* __restrict__ W2,
           float* __restrict__ out, int N) {
    __shared__ float s_in [MT * RPAD];          // 16.9 KB
    __shared__ float s_agg[MT * RPAD];          // 16.9 KB

    const int t  = threadIdx.x;
    const int m0 = blockIdx.x * MT;
    const int nv = min(MT, N - m0);

    // ---- stage input tile (coalesced float4) ----
    for (int i = t; i < MT * (IND / 4); i += NTH) {
        int m = i >> 5, j = i & 31;
        float4 v = make_float4(0.f, 0.f, 0.f, 0.f);
        if (m < nv) v = ((const float4*)input)[(size_t)(m0 + m) * 32 + j];
        ((float4*)(s_in + m * RPAD))[j] = v;
    }
    __syncthreads();

    // ================= attention phase (warp per node, 4 nodes/warp) ========
    {
        const int w = t >> 5, lane = t & 31;
        const float4 w2a4 = ((const float4*)g_w2a)[lane];
        const float4 wax4 = ((const float4*)g_wax)[lane];
        const float  ae   = a[2 * OUTD + lane];

        for (int j = 0; j < 4; ++j) {
            const int local = w * 4 + j;
            const int n     = m0 + local;
            if (n >= N) break;                  // warp-uniform

            const float4* nb = (const float4*)neigh + (size_t)n * (SS * IND / 4);
            const float*  eb = ee + (size_t)n * (SS * ED);

            // prefetch ring
            float4 v[PF]; float ev[PF];
#pragma unroll
            for (int i = 0; i < PF; ++i) {
                v[i]  = nb[i * (IND / 4) + lane];
                ev[i] = eb[i * ED + lane];
            }

            // sx = input_row . (W @ a_x)   (input from smem)
            float4 xi = ((const float4*)(s_in + local * RPAD))[lane];
            float p = xi.x * wax4.x;
            p = fmaf(xi.y, wax4.y, p);
            p = fmaf(xi.z, wax4.z, p);
            p = fmaf(xi.w, wax4.w, p);
#pragma unroll
            for (int o = 16; o; o >>= 1) p += __shfl_xor_sync(0xffffffffu, p, o);
            const float sx = p;

            float  mval = -3.0e38f, den = 0.f, he = 0.f;
            float4 agg  = make_float4(0.f, 0.f, 0.f, 0.f);

#pragma unroll
            for (int s = 0; s < SS; ++s) {
                const int slot = s & (PF - 1);
                float4 cv = v[slot];
                float  ce = ev[slot];
                if (s + PF < SS) {              // refill ring
                    v[slot]  = nb[(s + PF) * (IND / 4) + lane];
                    ev[slot] = eb[(s + PF) * ED + lane];
                }

                float part = cv.x * w2a4.x;
                part = fmaf(cv.y, w2a4.y, part);
                part = fmaf(cv.z, w2a4.z, part);
                part = fmaf(cv.w, w2a4.w, part);
                part = fmaf(ce, ae, part);
#pragma unroll
                for (int o = 16; o; o >>= 1) part += __shfl_xor_sync(0xffffffffu, part, o);

                float sc = part + sx;
                sc = sc > 0.f ? sc : 0.8f * sc; // leaky relu

                float mn   = fmaxf(mval, sc);
                float corr = __expf(mval - mn);
                float pe   = __expf(sc - mn);
                den   = fmaf(den,   corr, pe);
                agg.x = fmaf(agg.x, corr, pe * cv.x);
                agg.y = fmaf(agg.y, corr, pe * cv.y);
                agg.z = fmaf(agg.z, corr, pe * cv.z);
                agg.w = fmaf(agg.w, corr, pe * cv.w);
                he    = fmaf(he,    corr, pe * ce);
                mval = mn;
            }

            const float inv = 1.f / den;
            float4 o4 = make_float4(agg.x * inv, agg.y * inv, agg.z * inv, agg.w * inv);
            ((float4*)(s_agg + local * RPAD))[lane] = o4;
            out[(size_t)n * OSTR + 2 * OUTD + lane] = he * inv;   // h_edge
        }
    }
    __syncthreads();

    // ================= dual GEMM phase ======================================
    // 32 rows x 128 output cols: cols 0..63 = s_in@W, 64..127 = s_agg@W2.
    // Thread: row-group mg (4 rows) x col-group cg (4 cols). 16 accs.
    {
        const int cg  = t & 31, mg = t >> 5;
        const int c0g = cg * 4;                 // global output col
        const float* wp;
        const float* xb;
        if (c0g < OUTD) { wp = W  + c0g;          xb = s_in  + mg * 4 * RPAD; }
        else            { wp = W2 + (c0g - OUTD); xb = s_agg + mg * 4 * RPAD; }

        float acc[4][4];
#pragma unroll
        for (int r = 0; r < 4; ++r)
#pragma unroll
            for (int c = 0; c < 4; ++c) acc[r][c] = 0.f;

        float4 wv = *(const float4*)wp;         // k = 0 prefetch
#pragma unroll 4
        for (int k = 0; k < IND; ++k) {
            float4 wn;
            if (k + 1 < IND) wn = *(const float4*)(wp + (k + 1) * OUTD);
            float xv[4];
#pragma unroll
            for (int r = 0; r < 4; ++r) xv[r] = xb[r * RPAD + k];   // LDS broadcast
#pragma unroll
            for (int r = 0; r < 4; ++r) {
                acc[r][0] = fmaf(xv[r], wv.x, acc[r][0]);
                acc[r][1] = fmaf(xv[r], wv.y, acc[r][1]);
                acc[r][2] = fmaf(xv[r], wv.z, acc[r][2]);
                acc[r][3] = fmaf(xv[r], wv.w, acc[r][3]);
            }
            wv = wn;
        }

#pragma unroll
        for (int r = 0; r < 4; ++r) {
            int m = mg * 4 + r;
            if (m < nv)
                *(float4*)(out + (size_t)(m0 + m) * OSTR + c0g) = *(float4*)acc[r];
        }
    }
}

// ---------------------------------------------------------------------------
extern "C" void kernel_launch(void* const* d_in, const int* in_sizes, int n_in,
                              void* d_out, int out_size) {
    const float* input = (const float*)d_in[0];
    const float* neigh = (const float*)d_in[1];
    const float* ee    = (const float*)d_in[2];
    const float* W     = (const float*)d_in[3];
    const float* W2    = (const float*)d_in[4];
    const float* a     = (const float*)d_in[5];
    float* out = (float*)d_out;

    const int N = in_sizes[0] / IND;            // 50000

    prelude<<<1, 128>>>(W, W2, a);
    fused<<<(N + MT - 1) / MT, NTH>>>(input, neigh, ee, a, W, W2, out, N);
}